// round 11
// baseline (speedup 1.0000x reference)
#include <cuda_runtime.h>
#include <cuda_fp16.h>
#include <cstddef>
#include <cstdint>

#define NNODES 100000
#define EDGES  1600000
#define HDIM   128

// ---------------- scratch (device globals) -----------------------------------
__device__ __align__(256) __half g_xh    [(size_t)NNODES * HDIM];   // feat fp16 / later z fp16
__device__ __align__(256) __half g_h16   [(size_t)NNODES * HDIM];
__device__ __align__(256) __half g_hp_ppi[(size_t)NNODES * HDIM];
__device__ __align__(256) __half g_hp_sim[(size_t)NNODES * HDIM];
__device__ __align__(256) __half g_wh[4 * HDIM * HDIM];
__device__ __align__(256) int2   g_edges_p[EDGES];
__device__ __align__(256) int2   g_edges_s[EDGES];
// [deg_out_p | deg_in_p | deg_out_s | deg_in_s | cursor_p | cursor_s]
__device__ __align__(256) int    g_ints[6 * NNODES];
__device__ __align__(256) int    g_offs[2 * NNODES];

// ---------------- CSR build ---------------------------------------------------

__global__ void zero_ints_kernel(int4* __restrict__ p, int n4) {
    int i = blockIdx.x * blockDim.x + threadIdx.x;
    if (i < n4) p[i] = make_int4(0, 0, 0, 0);
}

__global__ void deg2_kernel(const int* __restrict__ src_p, const int* __restrict__ dst_p,
                            const int* __restrict__ src_s, const int* __restrict__ dst_s,
                            int* __restrict__ ints, int n, int e) {
    int i = blockIdx.x * blockDim.x + threadIdx.x;
    if (i < e) {
        atomicAdd(&ints[src_p[i]], 1);
        atomicAdd(&ints[n + dst_p[i]], 1);
    } else if (i < 2 * e) {
        int j = i - e;
        atomicAdd(&ints[2 * n + src_s[j]], 1);
        atomicAdd(&ints[3 * n + dst_s[j]], 1);
    }
}

// scan of deg_in per relation -> offs; also initializes cursor copy
__global__ void scan_full_kernel(const int* __restrict__ din0, const int* __restrict__ din1,
                                 int* __restrict__ offs, int* __restrict__ ints, int n) {
    const int CH = 98;
    const int* din = blockIdx.x ? din1 : din0;
    int* out  = offs + blockIdx.x * NNODES;
    int* curs = ints + (4 + blockIdx.x) * n;
    int t = threadIdx.x;
    int base = t * CH;

    int sum = 0;
    for (int k = 0; k < CH; k++) {
        int i = base + k;
        if (i < n) sum += din[i];
    }
    int lane = t & 31, wid = t >> 5;
    int incl = sum;
#pragma unroll
    for (int o = 1; o < 32; o <<= 1) {
        int v = __shfl_up_sync(0xffffffffu, incl, o);
        if (lane >= o) incl += v;
    }
    __shared__ int wsum[32];
    if (lane == 31) wsum[wid] = incl;
    __syncthreads();
    if (wid == 0) {
        int v = wsum[lane];
#pragma unroll
        for (int o = 1; o < 32; o <<= 1) {
            int u = __shfl_up_sync(0xffffffffu, v, o);
            if (lane >= o) v += u;
        }
        wsum[lane] = v;
    }
    __syncthreads();
    int run = (incl - sum) + (wid ? wsum[wid - 1] : 0);
    for (int k = 0; k < CH; k++) {
        int i = base + k;
        if (i < n) {
            out[i] = run;
            curs[i] = run;
            run += din[i];
        }
    }
}

// slot-scatter via cursor (no offs read), both relations
__global__ void sort2_kernel(const int* __restrict__ src_p, const int* __restrict__ dst_p,
                             const int* __restrict__ src_s, const int* __restrict__ dst_s,
                             int* __restrict__ ints, int2* __restrict__ edges_p,
                             int2* __restrict__ edges_s, int n, int e) {
    int i = blockIdx.x * blockDim.x + threadIdx.x;
    if (i < e) {
        int s = src_p[i], d = dst_p[i];
        float c = rsqrtf(fmaxf((float)ints[s], 1.0f)) * rsqrtf(fmaxf((float)ints[n + d], 1.0f));
        int slot = atomicAdd(&ints[4 * n + d], 1);
        edges_p[slot] = make_int2(s, __float_as_int(c));
    } else if (i < 2 * e) {
        int j = i - e;
        int s = src_s[j], d = dst_s[j];
        float c = rsqrtf(fmaxf((float)ints[2 * n + s], 1.0f)) * rsqrtf(fmaxf((float)ints[3 * n + d], 1.0f));
        int slot = atomicAdd(&ints[5 * n + d], 1);
        edges_s[slot] = make_int2(s, __float_as_int(c));
    }
}

// ---------------- fp32 -> fp16 convert (feat + all 4 weights) -----------------
__global__ void convert_all_kernel(const float* __restrict__ x, __half* __restrict__ xh,
                                   const float* __restrict__ w0p, const float* __restrict__ w0s,
                                   const float* __restrict__ w1p, const float* __restrict__ w1s,
                                   __half* __restrict__ wh, int n4x) {
    int i = blockIdx.x * blockDim.x + threadIdx.x;
    if (i < n4x) {
        float4 v = ((const float4*)x)[i];
        __half2 h[2];
        h[0] = __floats2half2_rn(v.x, v.y);
        h[1] = __floats2half2_rn(v.z, v.w);
        ((uint2*)xh)[i] = *(uint2*)h;
    } else {
        int j = i - n4x;
        if (j < 4 * (HDIM * HDIM / 4)) {
            int wsel = j >> 12, idx = j & 4095;
            const float* w = wsel == 0 ? w0p : wsel == 1 ? w0s : wsel == 2 ? w1p : w1s;
            float4 v = ((const float4*)w)[idx];
            __half2 h[2];
            h[0] = __floats2half2_rn(v.x, v.y);
            h[1] = __floats2half2_rn(v.z, v.w);
            ((uint2*)(wh + (size_t)wsel * HDIM * HDIM))[idx] = *(uint2*)h;
        }
    }
}

// ---------------- HMMA GEMM: 128-row tile, both weights in one launch --------
__global__ __launch_bounds__(256) void gemm_mma2_kernel(const __half* __restrict__ X,
                                                        const __half* __restrict__ Wa,
                                                        const __half* __restrict__ Wb,
                                                        __half* __restrict__ Ya,
                                                        __half* __restrict__ Yb, int nrows) {
    const __half* W = blockIdx.y ? Wb : Wa;
    __half* Y       = blockIdx.y ? Yb : Ya;

    __shared__ __align__(16) __half Xs[128][40];
    __shared__ __align__(16) __half Ws[32][136];
    const int tid  = threadIdx.x;
    const int warp = tid >> 5, lane = tid & 31;
    const int row0 = blockIdx.x * 128;
    const int wrow = warp * 16;

    float acc[16][4];
#pragma unroll
    for (int t = 0; t < 16; t++)
#pragma unroll
        for (int j = 0; j < 4; j++) acc[t][j] = 0.f;

    for (int k0 = 0; k0 < HDIM; k0 += 32) {
#pragma unroll
        for (int t = tid; t < 512; t += 256) {
            int r = t >> 2, c8 = (t & 3) * 8;
            int gr = row0 + r;
            uint4 v = make_uint4(0u, 0u, 0u, 0u);
            if (gr < nrows) v = *(const uint4*)(X + (size_t)gr * HDIM + k0 + c8);
            *(uint4*)&Xs[r][c8] = v;
        }
#pragma unroll
        for (int t = tid; t < 512; t += 256) {
            int r = t >> 4, c8 = (t & 15) * 8;
            *(uint4*)&Ws[r][c8] = *(const uint4*)(W + (size_t)(k0 + r) * HDIM + c8);
        }
        __syncthreads();
#pragma unroll
        for (int ks = 0; ks < 2; ks++) {
            const int kk = ks * 16;
            uint32_t a[4];
            {
                const __half* pa = &Xs[wrow + (lane & 7) + 8 * ((lane >> 3) & 1)][kk + 8 * (lane >> 4)];
                uint32_t addr = (uint32_t)__cvta_generic_to_shared(pa);
                asm volatile("ldmatrix.sync.aligned.m8n8.x4.shared.b16 {%0,%1,%2,%3}, [%4];"
                             : "=r"(a[0]), "=r"(a[1]), "=r"(a[2]), "=r"(a[3]) : "r"(addr));
            }
#pragma unroll
            for (int nt = 0; nt < 8; nt++) {
                const int n0 = nt * 16;
                uint32_t b[4];
                const __half* pb = &Ws[kk + (lane & 7) + 8 * ((lane >> 3) & 1)][n0 + 8 * (lane >> 4)];
                uint32_t addr = (uint32_t)__cvta_generic_to_shared(pb);
                asm volatile("ldmatrix.sync.aligned.m8n8.x4.trans.shared.b16 {%0,%1,%2,%3}, [%4];"
                             : "=r"(b[0]), "=r"(b[1]), "=r"(b[2]), "=r"(b[3]) : "r"(addr));
                asm volatile("mma.sync.aligned.m16n8k16.row.col.f32.f16.f16.f32 "
                             "{%0,%1,%2,%3}, {%4,%5,%6,%7}, {%8,%9}, {%0,%1,%2,%3};"
                             : "+f"(acc[2 * nt][0]), "+f"(acc[2 * nt][1]),
                               "+f"(acc[2 * nt][2]), "+f"(acc[2 * nt][3])
                             : "r"(a[0]), "r"(a[1]), "r"(a[2]), "r"(a[3]), "r"(b[0]), "r"(b[1]));
                asm volatile("mma.sync.aligned.m16n8k16.row.col.f32.f16.f16.f32 "
                             "{%0,%1,%2,%3}, {%4,%5,%6,%7}, {%8,%9}, {%0,%1,%2,%3};"
                             : "+f"(acc[2 * nt + 1][0]), "+f"(acc[2 * nt + 1][1]),
                               "+f"(acc[2 * nt + 1][2]), "+f"(acc[2 * nt + 1][3])
                             : "r"(a[0]), "r"(a[1]), "r"(a[2]), "r"(a[3]), "r"(b[2]), "r"(b[3]));
            }
        }
        __syncthreads();
    }
    const int rlo = row0 + wrow + (lane >> 2);
    const int rhi = rlo + 8;
    const int cbase = (lane & 3) * 2;
#pragma unroll
    for (int nt = 0; nt < 16; nt++) {
        int c = nt * 8 + cbase;
        if (rlo < nrows)
            *(__half2*)(Y + (size_t)rlo * HDIM + c) = __floats2half2_rn(acc[nt][0], acc[nt][1]);
        if (rhi < nrows)
            *(__half2*)(Y + (size_t)rhi * HDIM + c) = __floats2half2_rn(acc[nt][2], acc[nt][3]);
    }
}

// ---------------- fused aggregate (fp16 gathers, fp32 accum, 4-wide MLP) -----
template <typename OutT>
__global__ void aggregate_kernel(const __half* __restrict__ hp_p, const __half* __restrict__ hp_s,
                                 const int2* __restrict__ ep, const int* __restrict__ offs_p,
                                 const int* __restrict__ deg_p,
                                 const int2* __restrict__ es, const int* __restrict__ offs_s,
                                 const int* __restrict__ deg_s,
                                 const float* __restrict__ bp, const float* __restrict__ bs,
                                 OutT* __restrict__ out, __half* __restrict__ aux, int n) {
    int w = (blockIdx.x * blockDim.x + threadIdx.x) >> 5;
    int lane = threadIdx.x & 31;
    if (w >= n) return;
    float4 v = make_float4(0.f, 0.f, 0.f, 0.f);

#pragma unroll 1
    for (int rel = 0; rel < 2; rel++) {
        const int2* ed = rel ? es : ep;
        const __half* hp = rel ? hp_s : hp_p;
        int st = rel ? offs_s[w] : offs_p[w];
        int en = st + (rel ? deg_s[w] : deg_p[w]);
        int j = st;
        for (; j + 3 < en; j += 4) {
            int2 e0 = __ldg(&ed[j]);
            int2 e1 = __ldg(&ed[j + 1]);
            int2 e2 = __ldg(&ed[j + 2]);
            int2 e3 = __ldg(&ed[j + 3]);
            uint2 r0 = __ldg((const uint2*)(hp + (size_t)e0.x * HDIM) + lane);
            uint2 r1 = __ldg((const uint2*)(hp + (size_t)e1.x * HDIM) + lane);
            uint2 r2 = __ldg((const uint2*)(hp + (size_t)e2.x * HDIM) + lane);
            uint2 r3 = __ldg((const uint2*)(hp + (size_t)e3.x * HDIM) + lane);
            float c0 = __int_as_float(e0.y), c1 = __int_as_float(e1.y);
            float c2 = __int_as_float(e2.y), c3 = __int_as_float(e3.y);
            float2 a0 = __half22float2(*(__half2*)&r0.x), a1 = __half22float2(*(__half2*)&r0.y);
            float2 b0 = __half22float2(*(__half2*)&r1.x), b1 = __half22float2(*(__half2*)&r1.y);
            float2 d0 = __half22float2(*(__half2*)&r2.x), d1 = __half22float2(*(__half2*)&r2.y);
            float2 f0 = __half22float2(*(__half2*)&r3.x), f1 = __half22float2(*(__half2*)&r3.y);
            v.x += c0 * a0.x + c1 * b0.x + c2 * d0.x + c3 * f0.x;
            v.y += c0 * a0.y + c1 * b0.y + c2 * d0.y + c3 * f0.y;
            v.z += c0 * a1.x + c1 * b1.x + c2 * d1.x + c3 * f1.x;
            v.w += c0 * a1.y + c1 * b1.y + c2 * d1.y + c3 * f1.y;
        }
        for (; j < en; j++) {
            int2 e0 = __ldg(&ed[j]);
            uint2 r0 = __ldg((const uint2*)(hp + (size_t)e0.x * HDIM) + lane);
            float c0 = __int_as_float(e0.y);
            float2 a0 = __half22float2(*(__half2*)&r0.x);
            float2 a1 = __half22float2(*(__half2*)&r0.y);
            v.x += c0 * a0.x; v.y += c0 * a0.y; v.z += c0 * a1.x; v.w += c0 * a1.y;
        }
    }
    float4 b1 = ((const float4*)bp)[lane];
    float4 b2 = ((const float4*)bs)[lane];
    float4 r;
    r.x = fmaxf(0.5f * (v.x + b1.x + b2.x), 0.f);
    r.y = fmaxf(0.5f * (v.y + b1.y + b2.y), 0.f);
    r.z = fmaxf(0.5f * (v.z + b1.z + b2.z), 0.f);
    r.w = fmaxf(0.5f * (v.w + b1.w + b2.w), 0.f);
    if (sizeof(OutT) == 4) {
        *((float4*)((float*)out + (size_t)w * HDIM) + lane) = r;
        if (aux) {
            __half2 h[2];
            h[0] = __floats2half2_rn(r.x, r.y);
            h[1] = __floats2half2_rn(r.z, r.w);
            *((uint2*)(aux + (size_t)w * HDIM) + lane) = *(uint2*)h;
        }
    } else {
        __half2 h[2];
        h[0] = __floats2half2_rn(r.x, r.y);
        h[1] = __floats2half2_rn(r.z, r.w);
        *((uint2*)((__half*)out + (size_t)w * HDIM) + lane) = *(uint2*)h;
    }
}

// ---------------- pair classifier (fp16 z gather) -----------------------------
__global__ void pair_kernel(const __half* __restrict__ zh,
                            const int* __restrict__ ps, const int* __restrict__ pd,
                            const float* __restrict__ Wc, const float* __restrict__ bc,
                            float* __restrict__ out, int p) {
    int w = (blockIdx.x * blockDim.x + threadIdx.x) >> 5;
    int lane = threadIdx.x & 31;
    if (w >= p) return;
    int s = __ldg(&ps[w]), d = __ldg(&pd[w]);
    uint2 rs = __ldg((const uint2*)(zh + (size_t)s * HDIM) + lane);
    uint2 rd = __ldg((const uint2*)(zh + (size_t)d * HDIM) + lane);
    float2 zs0 = __half22float2(*(__half2*)&rs.x), zs1 = __half22float2(*(__half2*)&rs.y);
    float2 zd0 = __half22float2(*(__half2*)&rd.x), zd1 = __half22float2(*(__half2*)&rd.y);
    const float4* wc4 = (const float4*)Wc;
    float4 wa = wc4[lane * 2], wb = wc4[lane * 2 + 1];
    float l0 = zs0.x * wa.x + zs0.y * wa.z + zs1.x * wb.x + zs1.y * wb.z;
    float l1 = zs0.x * wa.y + zs0.y * wa.w + zs1.x * wb.y + zs1.y * wb.w;
    float4 wcv = wc4[64 + lane * 2], wd = wc4[64 + lane * 2 + 1];
    l0 += zd0.x * wcv.x + zd0.y * wcv.z + zd1.x * wd.x + zd1.y * wd.z;
    l1 += zd0.x * wcv.y + zd0.y * wcv.w + zd1.x * wd.y + zd1.y * wd.w;
#pragma unroll
    for (int o = 16; o; o >>= 1) {
        l0 += __shfl_xor_sync(0xffffffffu, l0, o);
        l1 += __shfl_xor_sync(0xffffffffu, l1, o);
    }
    if (lane == 0) {
        out[(size_t)w * 2] = l0 + bc[0];
        out[(size_t)w * 2 + 1] = l1 + bc[1];
    }
}

// ---------------- launch -----------------------------------------------------

extern "C" void kernel_launch(void* const* d_in, const int* in_sizes, int n_in,
                              void* d_out, int out_size) {
    const float* feat   = (const float*)d_in[0];
    const int* src_ppi  = (const int*)d_in[1];
    const int* dst_ppi  = (const int*)d_in[2];
    const int* src_sim  = (const int*)d_in[3];
    const int* dst_sim  = (const int*)d_in[4];
    const int* pair_src = (const int*)d_in[5];
    const int* pair_dst = (const int*)d_in[6];
    const float* W0_ppi = (const float*)d_in[7];
    const float* b0_ppi = (const float*)d_in[8];
    const float* W0_sim = (const float*)d_in[9];
    const float* b0_sim = (const float*)d_in[10];
    const float* W1_ppi = (const float*)d_in[11];
    const float* b1_ppi = (const float*)d_in[12];
    const float* W1_sim = (const float*)d_in[13];
    const float* b1_sim = (const float*)d_in[14];
    const float* Wc     = (const float*)d_in[15];
    const float* bc     = (const float*)d_in[16];

    const int n = in_sizes[0] / HDIM;
    const int e = in_sizes[1];
    const int p = in_sizes[5];

    float* zout   = (float*)d_out;
    float* logits = (float*)d_out + (size_t)n * HDIM;

    __half *xh, *h16, *hp_ppi, *hp_sim, *wh;
    int *ints, *offs;
    int2 *edges_p, *edges_s;
    cudaGetSymbolAddress((void**)&xh,      g_xh);
    cudaGetSymbolAddress((void**)&h16,     g_h16);
    cudaGetSymbolAddress((void**)&hp_ppi,  g_hp_ppi);
    cudaGetSymbolAddress((void**)&hp_sim,  g_hp_sim);
    cudaGetSymbolAddress((void**)&wh,      g_wh);
    cudaGetSymbolAddress((void**)&ints,    g_ints);
    cudaGetSymbolAddress((void**)&offs,    g_offs);
    cudaGetSymbolAddress((void**)&edges_p, g_edges_p);
    cudaGetSymbolAddress((void**)&edges_s, g_edges_s);

    int* deg_in_p = ints + n;
    int* deg_in_s = ints + 3 * n;
    int* offs_p = offs;
    int* offs_s = offs + NNODES;

    __half* w0p = wh;
    __half* w0s = wh + HDIM * HDIM;
    __half* w1p = wh + 2 * HDIM * HDIM;
    __half* w1s = wh + 3 * HDIM * HDIM;

    const int TB = 256;
    const int nh = n * HDIM;
    const int n4x = nh / 4;
    const int e2_blocks   = (2 * e + TB - 1) / TB;
    const int zero_blocks = (n + TB - 1) / TB;
    const int cv_blocks   = (n4x + 4 * (HDIM * HDIM / 4) + TB - 1) / TB;
    const int agg_blocks  = (int)(((long long)n * 32 + TB - 1) / TB);
    const int pair_blocks = (int)(((long long)p * 32 + TB - 1) / TB);
    dim3 gemm_grid((n + 127) / 128, 2);

    // ---- CSR build ----
    zero_ints_kernel<<<zero_blocks, TB>>>((int4*)ints, n);
    deg2_kernel<<<e2_blocks, TB>>>(src_ppi, dst_ppi, src_sim, dst_sim, ints, n, e);
    scan_full_kernel<<<2, 1024>>>(deg_in_p, deg_in_s, offs, ints, n);
    sort2_kernel<<<e2_blocks, TB>>>(src_ppi, dst_ppi, src_sim, dst_sim, ints,
                                    edges_p, edges_s, n, e);

    // ---- fp16 conversion (feat + weights), as R7 ----
    convert_all_kernel<<<cv_blocks, TB>>>(feat, xh, W0_ppi, W0_sim, W1_ppi, W1_sim, wh, n4x);

    // ---- layer 0 ----
    gemm_mma2_kernel<<<gemm_grid, 256>>>(xh, w0p, w0s, hp_ppi, hp_sim, n);
    aggregate_kernel<__half><<<agg_blocks, TB>>>(hp_ppi, hp_sim, edges_p, offs_p, deg_in_p,
                                                 edges_s, offs_s, deg_in_s, b0_ppi, b0_sim,
                                                 h16, (__half*)0, n);

    // ---- layer 1 (agg writes fp32 zout + fp16 copy into xh, now free) ----
    gemm_mma2_kernel<<<gemm_grid, 256>>>(h16, w1p, w1s, hp_ppi, hp_sim, n);
    aggregate_kernel<float><<<agg_blocks, TB>>>(hp_ppi, hp_sim, edges_p, offs_p, deg_in_p,
                                                edges_s, offs_s, deg_in_s, b1_ppi, b1_sim,
                                                zout, xh, n);

    // ---- pair classifier (fp16 z) ----
    pair_kernel<<<pair_blocks, TB>>>(xh, pair_src, pair_dst, Wc, bc, logits, p);
}

// round 12
// speedup vs baseline: 1.0079x; 1.0079x over previous
#include <cuda_runtime.h>
#include <cuda_fp16.h>
#include <cstddef>
#include <cstdint>

#define NNODES 100000
#define EDGES  1600000
#define HDIM   128

// ---------------- scratch (device globals) -----------------------------------
__device__ __align__(256) __half g_xh    [(size_t)NNODES * HDIM];
__device__ __align__(256) __half g_h16   [(size_t)NNODES * HDIM];
__device__ __align__(256) __half g_hp_ppi[(size_t)NNODES * HDIM];
__device__ __align__(256) __half g_hp_sim[(size_t)NNODES * HDIM];
__device__ __align__(256) __half g_wh[4 * HDIM * HDIM];
__device__ __align__(256) int2   g_edges_p[EDGES];
__device__ __align__(256) int2   g_edges_s[EDGES];
// [deg_out_p | deg_in_p | deg_out_s | deg_in_s | cursor_p | cursor_s]
__device__ __align__(256) int    g_ints[6 * NNODES];
__device__ __align__(256) int    g_offs[2 * NNODES];

// ---------------- CSR build ---------------------------------------------------

__global__ void zero_ints_kernel(int4* __restrict__ p, int n4) {
    int i = blockIdx.x * blockDim.x + threadIdx.x;
    if (i < n4) p[i] = make_int4(0, 0, 0, 0);
}

__global__ void deg2_kernel(const int* __restrict__ src_p, const int* __restrict__ dst_p,
                            const int* __restrict__ src_s, const int* __restrict__ dst_s,
                            int* __restrict__ ints, int n, int e) {
    int i = blockIdx.x * blockDim.x + threadIdx.x;
    if (i < e) {
        atomicAdd(&ints[src_p[i]], 1);
        atomicAdd(&ints[n + dst_p[i]], 1);
    } else if (i < 2 * e) {
        int j = i - e;
        atomicAdd(&ints[2 * n + src_s[j]], 1);
        atomicAdd(&ints[3 * n + dst_s[j]], 1);
    }
}

// scan of deg_in per relation -> offs; ALSO initializes cursor copy (the one change vs R7)
__global__ void scan_full_kernel(const int* __restrict__ din0, const int* __restrict__ din1,
                                 int* __restrict__ offs, int* __restrict__ ints, int n) {
    const int CH = 98;                       // 1024*98 >= 100000
    const int* din = blockIdx.x ? din1 : din0;
    int* out  = offs + blockIdx.x * NNODES;
    int* curs = ints + (4 + blockIdx.x) * n;
    int t = threadIdx.x;
    int base = t * CH;

    int sum = 0;
    for (int k = 0; k < CH; k++) {
        int i = base + k;
        if (i < n) sum += din[i];
    }
    int lane = t & 31, wid = t >> 5;
    int incl = sum;
#pragma unroll
    for (int o = 1; o < 32; o <<= 1) {
        int v = __shfl_up_sync(0xffffffffu, incl, o);
        if (lane >= o) incl += v;
    }
    __shared__ int wsum[32];
    if (lane == 31) wsum[wid] = incl;
    __syncthreads();
    if (wid == 0) {
        int v = wsum[lane];
#pragma unroll
        for (int o = 1; o < 32; o <<= 1) {
            int u = __shfl_up_sync(0xffffffffu, v, o);
            if (lane >= o) v += u;
        }
        wsum[lane] = v;
    }
    __syncthreads();
    int run = (incl - sum) + (wid ? wsum[wid - 1] : 0);
    for (int k = 0; k < CH; k++) {
        int i = base + k;
        if (i < n) {
            out[i] = run;
            curs[i] = run;
            run += din[i];
        }
    }
}

// slot-scatter via cursor (one atomic, no offs read), both relations
__global__ void sort2_kernel(const int* __restrict__ src_p, const int* __restrict__ dst_p,
                             const int* __restrict__ src_s, const int* __restrict__ dst_s,
                             int* __restrict__ ints, int2* __restrict__ edges_p,
                             int2* __restrict__ edges_s, int n, int e) {
    int i = blockIdx.x * blockDim.x + threadIdx.x;
    if (i < e) {
        int s = src_p[i], d = dst_p[i];
        float c = rsqrtf(fmaxf((float)ints[s], 1.0f)) * rsqrtf(fmaxf((float)ints[n + d], 1.0f));
        int slot = atomicAdd(&ints[4 * n + d], 1);
        edges_p[slot] = make_int2(s, __float_as_int(c));
    } else if (i < 2 * e) {
        int j = i - e;
        int s = src_s[j], d = dst_s[j];
        float c = rsqrtf(fmaxf((float)ints[2 * n + s], 1.0f)) * rsqrtf(fmaxf((float)ints[3 * n + d], 1.0f));
        int slot = atomicAdd(&ints[5 * n + d], 1);
        edges_s[slot] = make_int2(s, __float_as_int(c));
    }
}

// ---------------- fp32 -> fp16 convert (feat + all 4 weights, one launch) ----
__global__ void convert_all_kernel(const float* __restrict__ x, __half* __restrict__ xh,
                                   const float* __restrict__ w0p, const float* __restrict__ w0s,
                                   const float* __restrict__ w1p, const float* __restrict__ w1s,
                                   __half* __restrict__ wh, int n4x) {
    int i = blockIdx.x * blockDim.x + threadIdx.x;
    if (i < n4x) {
        float4 v = ((const float4*)x)[i];
        __half2 h[2];
        h[0] = __floats2half2_rn(v.x, v.y);
        h[1] = __floats2half2_rn(v.z, v.w);
        ((uint2*)xh)[i] = *(uint2*)h;
    } else {
        int j = i - n4x;
        if (j < 4 * (HDIM * HDIM / 4)) {
            int wsel = j >> 12, idx = j & 4095;
            const float* w = wsel == 0 ? w0p : wsel == 1 ? w0s : wsel == 2 ? w1p : w1s;
            float4 v = ((const float4*)w)[idx];
            __half2 h[2];
            h[0] = __floats2half2_rn(v.x, v.y);
            h[1] = __floats2half2_rn(v.z, v.w);
            ((uint2*)(wh + (size_t)wsel * HDIM * HDIM))[idx] = *(uint2*)h;
        }
    }
}

// ---------------- HMMA GEMM: both relation weights in one launch -------------
__global__ __launch_bounds__(256) void gemm_mma2_kernel(const __half* __restrict__ X,
                                                        const __half* __restrict__ Wa,
                                                        const __half* __restrict__ Wb,
                                                        __half* __restrict__ Ya,
                                                        __half* __restrict__ Yb, int nrows) {
    const __half* W = blockIdx.y ? Wb : Wa;
    __half* Y       = blockIdx.y ? Yb : Ya;

    __shared__ __half Xs[128][40];
    __shared__ __half Ws[32][136];
    const int tid  = threadIdx.x;
    const int warp = tid >> 5, lane = tid & 31;
    const int row0 = blockIdx.x * 128;
    const int wrow = warp * 16;

    float acc[16][4];
#pragma unroll
    for (int t = 0; t < 16; t++)
#pragma unroll
        for (int j = 0; j < 4; j++) acc[t][j] = 0.f;

    for (int k0 = 0; k0 < HDIM; k0 += 32) {
#pragma unroll
        for (int t = tid; t < 512; t += 256) {
            int r = t >> 2, c8 = (t & 3) * 8;
            int gr = row0 + r;
            uint4 v = make_uint4(0u, 0u, 0u, 0u);
            if (gr < nrows) v = *(const uint4*)(X + (size_t)gr * HDIM + k0 + c8);
            *(uint4*)&Xs[r][c8] = v;
        }
#pragma unroll
        for (int t = tid; t < 512; t += 256) {
            int r = t >> 4, c8 = (t & 15) * 8;
            *(uint4*)&Ws[r][c8] = *(const uint4*)(W + (size_t)(k0 + r) * HDIM + c8);
        }
        __syncthreads();
#pragma unroll
        for (int ks = 0; ks < 2; ks++) {
            const int kk = ks * 16;
            uint32_t a[4];
            {
                const __half* pa = &Xs[wrow + (lane & 7) + 8 * ((lane >> 3) & 1)][kk + 8 * (lane >> 4)];
                uint32_t addr = (uint32_t)__cvta_generic_to_shared(pa);
                asm volatile("ldmatrix.sync.aligned.m8n8.x4.shared.b16 {%0,%1,%2,%3}, [%4];"
                             : "=r"(a[0]), "=r"(a[1]), "=r"(a[2]), "=r"(a[3]) : "r"(addr));
            }
#pragma unroll
            for (int nt = 0; nt < 8; nt++) {
                const int n0 = nt * 16;
                uint32_t b[4];
                const __half* pb = &Ws[kk + (lane & 7) + 8 * ((lane >> 3) & 1)][n0 + 8 * (lane >> 4)];
                uint32_t addr = (uint32_t)__cvta_generic_to_shared(pb);
                asm volatile("ldmatrix.sync.aligned.m8n8.x4.trans.shared.b16 {%0,%1,%2,%3}, [%4];"
                             : "=r"(b[0]), "=r"(b[1]), "=r"(b[2]), "=r"(b[3]) : "r"(addr));
                asm volatile("mma.sync.aligned.m16n8k16.row.col.f32.f16.f16.f32 "
                             "{%0,%1,%2,%3}, {%4,%5,%6,%7}, {%8,%9}, {%0,%1,%2,%3};"
                             : "+f"(acc[2 * nt][0]), "+f"(acc[2 * nt][1]),
                               "+f"(acc[2 * nt][2]), "+f"(acc[2 * nt][3])
                             : "r"(a[0]), "r"(a[1]), "r"(a[2]), "r"(a[3]), "r"(b[0]), "r"(b[1]));
                asm volatile("mma.sync.aligned.m16n8k16.row.col.f32.f16.f16.f32 "
                             "{%0,%1,%2,%3}, {%4,%5,%6,%7}, {%8,%9}, {%0,%1,%2,%3};"
                             : "+f"(acc[2 * nt + 1][0]), "+f"(acc[2 * nt + 1][1]),
                               "+f"(acc[2 * nt + 1][2]), "+f"(acc[2 * nt + 1][3])
                             : "r"(a[0]), "r"(a[1]), "r"(a[2]), "r"(a[3]), "r"(b[2]), "r"(b[3]));
            }
        }
        __syncthreads();
    }
    const int rlo = row0 + wrow + (lane >> 2);
    const int rhi = rlo + 8;
    const int cbase = (lane & 3) * 2;
#pragma unroll
    for (int nt = 0; nt < 16; nt++) {
        int c = nt * 8 + cbase;
        if (rlo < nrows)
            *(__half2*)(Y + (size_t)rlo * HDIM + c) = __floats2half2_rn(acc[nt][0], acc[nt][1]);
        if (rhi < nrows)
            *(__half2*)(Y + (size_t)rhi * HDIM + c) = __floats2half2_rn(acc[nt][2], acc[nt][3]);
    }
}

// ---------------- fused aggregate (fp16 gathers, fp32 accum, 4-wide MLP) -----
template <typename OutT>
__global__ void aggregate_kernel(const __half* __restrict__ hp_p, const __half* __restrict__ hp_s,
                                 const int2* __restrict__ ep, const int* __restrict__ offs_p,
                                 const int* __restrict__ deg_p,
                                 const int2* __restrict__ es, const int* __restrict__ offs_s,
                                 const int* __restrict__ deg_s,
                                 const float* __restrict__ bp, const float* __restrict__ bs,
                                 OutT* __restrict__ out, int n) {
    int w = (blockIdx.x * blockDim.x + threadIdx.x) >> 5;
    int lane = threadIdx.x & 31;
    if (w >= n) return;
    float4 v = make_float4(0.f, 0.f, 0.f, 0.f);

#pragma unroll 1
    for (int rel = 0; rel < 2; rel++) {
        const int2* ed = rel ? es : ep;
        const __half* hp = rel ? hp_s : hp_p;
        int st = rel ? offs_s[w] : offs_p[w];
        int en = st + (rel ? deg_s[w] : deg_p[w]);
        int j = st;
        for (; j + 3 < en; j += 4) {
            int2 e0 = __ldg(&ed[j]);
            int2 e1 = __ldg(&ed[j + 1]);
            int2 e2 = __ldg(&ed[j + 2]);
            int2 e3 = __ldg(&ed[j + 3]);
            uint2 r0 = __ldg((const uint2*)(hp + (size_t)e0.x * HDIM) + lane);
            uint2 r1 = __ldg((const uint2*)(hp + (size_t)e1.x * HDIM) + lane);
            uint2 r2 = __ldg((const uint2*)(hp + (size_t)e2.x * HDIM) + lane);
            uint2 r3 = __ldg((const uint2*)(hp + (size_t)e3.x * HDIM) + lane);
            float c0 = __int_as_float(e0.y), c1 = __int_as_float(e1.y);
            float c2 = __int_as_float(e2.y), c3 = __int_as_float(e3.y);
            float2 a0 = __half22float2(*(__half2*)&r0.x), a1 = __half22float2(*(__half2*)&r0.y);
            float2 b0 = __half22float2(*(__half2*)&r1.x), b1 = __half22float2(*(__half2*)&r1.y);
            float2 d0 = __half22float2(*(__half2*)&r2.x), d1 = __half22float2(*(__half2*)&r2.y);
            float2 f0 = __half22float2(*(__half2*)&r3.x), f1 = __half22float2(*(__half2*)&r3.y);
            v.x += c0 * a0.x + c1 * b0.x + c2 * d0.x + c3 * f0.x;
            v.y += c0 * a0.y + c1 * b0.y + c2 * d0.y + c3 * f0.y;
            v.z += c0 * a1.x + c1 * b1.x + c2 * d1.x + c3 * f1.x;
            v.w += c0 * a1.y + c1 * b1.y + c2 * d1.y + c3 * f1.y;
        }
        for (; j < en; j++) {
            int2 e0 = __ldg(&ed[j]);
            uint2 r0 = __ldg((const uint2*)(hp + (size_t)e0.x * HDIM) + lane);
            float c0 = __int_as_float(e0.y);
            float2 a0 = __half22float2(*(__half2*)&r0.x);
            float2 a1 = __half22float2(*(__half2*)&r0.y);
            v.x += c0 * a0.x; v.y += c0 * a0.y; v.z += c0 * a1.x; v.w += c0 * a1.y;
        }
    }
    float4 b1 = ((const float4*)bp)[lane];
    float4 b2 = ((const float4*)bs)[lane];
    float4 r;
    r.x = fmaxf(0.5f * (v.x + b1.x + b2.x), 0.f);
    r.y = fmaxf(0.5f * (v.y + b1.y + b2.y), 0.f);
    r.z = fmaxf(0.5f * (v.z + b1.z + b2.z), 0.f);
    r.w = fmaxf(0.5f * (v.w + b1.w + b2.w), 0.f);
    if (sizeof(OutT) == 4) {
        *((float4*)((float*)out + (size_t)w * HDIM) + lane) = r;
    } else {
        __half2 h[2];
        h[0] = __floats2half2_rn(r.x, r.y);
        h[1] = __floats2half2_rn(r.z, r.w);
        *((uint2*)((__half*)out + (size_t)w * HDIM) + lane) = *(uint2*)h;
    }
}

// ---------------- pair classifier (fp32 z gather, as R7) ----------------------
__global__ void pair_kernel(const float* __restrict__ z,
                            const int* __restrict__ ps, const int* __restrict__ pd,
                            const float* __restrict__ Wc, const float* __restrict__ bc,
                            float* __restrict__ out, int p) {
    int w = (blockIdx.x * blockDim.x + threadIdx.x) >> 5;
    int lane = threadIdx.x & 31;
    if (w >= p) return;
    int s = __ldg(&ps[w]), d = __ldg(&pd[w]);
    float4 zs = __ldg((const float4*)(z + (size_t)s * HDIM) + lane);
    float4 zd = __ldg((const float4*)(z + (size_t)d * HDIM) + lane);
    const float4* wc4 = (const float4*)Wc;
    float4 wa = wc4[lane * 2], wb = wc4[lane * 2 + 1];
    float l0 = zs.x * wa.x + zs.y * wa.z + zs.z * wb.x + zs.w * wb.z;
    float l1 = zs.x * wa.y + zs.y * wa.w + zs.z * wb.y + zs.w * wb.w;
    float4 wcv = wc4[64 + lane * 2], wd = wc4[64 + lane * 2 + 1];
    l0 += zd.x * wcv.x + zd.y * wcv.z + zd.z * wd.x + zd.w * wd.z;
    l1 += zd.x * wcv.y + zd.y * wcv.w + zd.z * wd.y + zd.w * wd.w;
#pragma unroll
    for (int o = 16; o; o >>= 1) {
        l0 += __shfl_xor_sync(0xffffffffu, l0, o);
        l1 += __shfl_xor_sync(0xffffffffu, l1, o);
    }
    if (lane == 0) {
        out[(size_t)w * 2] = l0 + bc[0];
        out[(size_t)w * 2 + 1] = l1 + bc[1];
    }
}

// ---------------- launch -----------------------------------------------------

extern "C" void kernel_launch(void* const* d_in, const int* in_sizes, int n_in,
                              void* d_out, int out_size) {
    const float* feat   = (const float*)d_in[0];
    const int* src_ppi  = (const int*)d_in[1];
    const int* dst_ppi  = (const int*)d_in[2];
    const int* src_sim  = (const int*)d_in[3];
    const int* dst_sim  = (const int*)d_in[4];
    const int* pair_src = (const int*)d_in[5];
    const int* pair_dst = (const int*)d_in[6];
    const float* W0_ppi = (const float*)d_in[7];
    const float* b0_ppi = (const float*)d_in[8];
    const float* W0_sim = (const float*)d_in[9];
    const float* b0_sim = (const float*)d_in[10];
    const float* W1_ppi = (const float*)d_in[11];
    const float* b1_ppi = (const float*)d_in[12];
    const float* W1_sim = (const float*)d_in[13];
    const float* b1_sim = (const float*)d_in[14];
    const float* Wc     = (const float*)d_in[15];
    const float* bc     = (const float*)d_in[16];

    const int n = in_sizes[0] / HDIM;
    const int e = in_sizes[1];
    const int p = in_sizes[5];

    float* zout   = (float*)d_out;
    float* logits = (float*)d_out + (size_t)n * HDIM;

    __half *xh, *h16, *hp_ppi, *hp_sim, *wh;
    int *ints, *offs;
    int2 *edges_p, *edges_s;
    cudaGetSymbolAddress((void**)&xh,      g_xh);
    cudaGetSymbolAddress((void**)&h16,     g_h16);
    cudaGetSymbolAddress((void**)&hp_ppi,  g_hp_ppi);
    cudaGetSymbolAddress((void**)&hp_sim,  g_hp_sim);
    cudaGetSymbolAddress((void**)&wh,      g_wh);
    cudaGetSymbolAddress((void**)&ints,    g_ints);
    cudaGetSymbolAddress((void**)&offs,    g_offs);
    cudaGetSymbolAddress((void**)&edges_p, g_edges_p);
    cudaGetSymbolAddress((void**)&edges_s, g_edges_s);

    int* deg_in_p = ints + n;
    int* deg_in_s = ints + 3 * n;
    int* offs_p = offs;
    int* offs_s = offs + NNODES;

    __half* w0p = wh;
    __half* w0s = wh + HDIM * HDIM;
    __half* w1p = wh + 2 * HDIM * HDIM;
    __half* w1s = wh + 3 * HDIM * HDIM;

    const int TB = 256;
    const int nh = n * HDIM;
    const int n4x = nh / 4;
    const int e2_blocks   = (2 * e + TB - 1) / TB;
    const int zero_blocks = (n + TB - 1) / TB;     // 4n ints as n int4 (cursors set by scan)
    const int cv_blocks   = (n4x + 4 * (HDIM * HDIM / 4) + TB - 1) / TB;
    const int agg_blocks  = (int)(((long long)n * 32 + TB - 1) / TB);
    const int pair_blocks = (int)(((long long)p * 32 + TB - 1) / TB);
    dim3 gemm_grid((n + 127) / 128, 2);

    // ---- CSR build ----
    zero_ints_kernel<<<zero_blocks, TB>>>((int4*)ints, n);
    deg2_kernel<<<e2_blocks, TB>>>(src_ppi, dst_ppi, src_sim, dst_sim, ints, n, e);
    scan_full_kernel<<<2, 1024>>>(deg_in_p, deg_in_s, offs, ints, n);
    sort2_kernel<<<e2_blocks, TB>>>(src_ppi, dst_ppi, src_sim, dst_sim, ints,
                                    edges_p, edges_s, n, e);

    // ---- fp16 conversion (feat + weights) ----
    convert_all_kernel<<<cv_blocks, TB>>>(feat, xh, W0_ppi, W0_sim, W1_ppi, W1_sim, wh, n4x);

    // ---- layer 0 ----
    gemm_mma2_kernel<<<gemm_grid, 256>>>(xh, w0p, w0s, hp_ppi, hp_sim, n);
    aggregate_kernel<__half><<<agg_blocks, TB>>>(hp_ppi, hp_sim, edges_p, offs_p, deg_in_p,
                                                 edges_s, offs_s, deg_in_s, b0_ppi, b0_sim, h16, n);

    // ---- layer 1 ----
    gemm_mma2_kernel<<<gemm_grid, 256>>>(h16, w1p, w1s, hp_ppi, hp_sim, n);
    aggregate_kernel<float><<<agg_blocks, TB>>>(hp_ppi, hp_sim, edges_p, offs_p, deg_in_p,
                                                edges_s, offs_s, deg_in_s, b1_ppi, b1_sim, zout, n);

    // ---- pair classifier ----
    pair_kernel<<<pair_blocks, TB>>>(zout, pair_src, pair_dst, Wc, bc, logits, p);
}

// round 13
// speedup vs baseline: 1.0105x; 1.0025x over previous
#include <cuda_runtime.h>
#include <cuda_fp16.h>
#include <cstddef>
#include <cstdint>

#define NNODES 100000
#define EDGES  1600000
#define HDIM   128

// ---------------- scratch (device globals) -----------------------------------
__device__ __align__(256) __half g_xh    [(size_t)NNODES * HDIM];   // feat fp16, later z fp16
__device__ __align__(256) __half g_h16   [(size_t)NNODES * HDIM];
__device__ __align__(256) __half g_hp_ppi[(size_t)NNODES * HDIM];
__device__ __align__(256) __half g_hp_sim[(size_t)NNODES * HDIM];
__device__ __align__(256) __half g_wh[4 * HDIM * HDIM];
__device__ __align__(256) int2   g_edges_p[EDGES];
__device__ __align__(256) int2   g_edges_s[EDGES];
// [deg_out_p | deg_in_p | deg_out_s | deg_in_s | cursor_p | cursor_s]
__device__ __align__(256) int    g_ints[6 * NNODES];
__device__ __align__(256) int    g_offs[2 * NNODES];

// ---------------- CSR build ---------------------------------------------------

__global__ void zero_ints_kernel(int4* __restrict__ p, int n4) {
    int i = blockIdx.x * blockDim.x + threadIdx.x;
    if (i < n4) p[i] = make_int4(0, 0, 0, 0);
}

__global__ void deg2_kernel(const int* __restrict__ src_p, const int* __restrict__ dst_p,
                            const int* __restrict__ src_s, const int* __restrict__ dst_s,
                            int* __restrict__ ints, int n, int e) {
    int i = blockIdx.x * blockDim.x + threadIdx.x;
    if (i < e) {
        atomicAdd(&ints[src_p[i]], 1);
        atomicAdd(&ints[n + dst_p[i]], 1);
    } else if (i < 2 * e) {
        int j = i - e;
        atomicAdd(&ints[2 * n + src_s[j]], 1);
        atomicAdd(&ints[3 * n + dst_s[j]], 1);
    }
}

// scan of deg_in per relation -> offs; also initializes cursor copy
__global__ void scan_full_kernel(const int* __restrict__ din0, const int* __restrict__ din1,
                                 int* __restrict__ offs, int* __restrict__ ints, int n) {
    const int CH = 98;
    const int* din = blockIdx.x ? din1 : din0;
    int* out  = offs + blockIdx.x * NNODES;
    int* curs = ints + (4 + blockIdx.x) * n;
    int t = threadIdx.x;
    int base = t * CH;

    int sum = 0;
    for (int k = 0; k < CH; k++) {
        int i = base + k;
        if (i < n) sum += din[i];
    }
    int lane = t & 31, wid = t >> 5;
    int incl = sum;
#pragma unroll
    for (int o = 1; o < 32; o <<= 1) {
        int v = __shfl_up_sync(0xffffffffu, incl, o);
        if (lane >= o) incl += v;
    }
    __shared__ int wsum[32];
    if (lane == 31) wsum[wid] = incl;
    __syncthreads();
    if (wid == 0) {
        int v = wsum[lane];
#pragma unroll
        for (int o = 1; o < 32; o <<= 1) {
            int u = __shfl_up_sync(0xffffffffu, v, o);
            if (lane >= o) v += u;
        }
        wsum[lane] = v;
    }
    __syncthreads();
    int run = (incl - sum) + (wid ? wsum[wid - 1] : 0);
    for (int k = 0; k < CH; k++) {
        int i = base + k;
        if (i < n) {
            out[i] = run;
            curs[i] = run;
            run += din[i];
        }
    }
}

// slot-scatter via cursor (one atomic, no offs read), both relations
__global__ void sort2_kernel(const int* __restrict__ src_p, const int* __restrict__ dst_p,
                             const int* __restrict__ src_s, const int* __restrict__ dst_s,
                             int* __restrict__ ints, int2* __restrict__ edges_p,
                             int2* __restrict__ edges_s, int n, int e) {
    int i = blockIdx.x * blockDim.x + threadIdx.x;
    if (i < e) {
        int s = src_p[i], d = dst_p[i];
        float c = rsqrtf(fmaxf((float)ints[s], 1.0f)) * rsqrtf(fmaxf((float)ints[n + d], 1.0f));
        int slot = atomicAdd(&ints[4 * n + d], 1);
        edges_p[slot] = make_int2(s, __float_as_int(c));
    } else if (i < 2 * e) {
        int j = i - e;
        int s = src_s[j], d = dst_s[j];
        float c = rsqrtf(fmaxf((float)ints[2 * n + s], 1.0f)) * rsqrtf(fmaxf((float)ints[3 * n + d], 1.0f));
        int slot = atomicAdd(&ints[5 * n + d], 1);
        edges_s[slot] = make_int2(s, __float_as_int(c));
    }
}

// ---------------- fp32 -> fp16 convert (feat + all 4 weights) -----------------
__global__ void convert_all_kernel(const float* __restrict__ x, __half* __restrict__ xh,
                                   const float* __restrict__ w0p, const float* __restrict__ w0s,
                                   const float* __restrict__ w1p, const float* __restrict__ w1s,
                                   __half* __restrict__ wh, int n4x) {
    int i = blockIdx.x * blockDim.x + threadIdx.x;
    if (i < n4x) {
        float4 v = ((const float4*)x)[i];
        __half2 h[2];
        h[0] = __floats2half2_rn(v.x, v.y);
        h[1] = __floats2half2_rn(v.z, v.w);
        ((uint2*)xh)[i] = *(uint2*)h;
    } else {
        int j = i - n4x;
        if (j < 4 * (HDIM * HDIM / 4)) {
            int wsel = j >> 12, idx = j & 4095;
            const float* w = wsel == 0 ? w0p : wsel == 1 ? w0s : wsel == 2 ? w1p : w1s;
            float4 v = ((const float4*)w)[idx];
            __half2 h[2];
            h[0] = __floats2half2_rn(v.x, v.y);
            h[1] = __floats2half2_rn(v.z, v.w);
            ((uint2*)(wh + (size_t)wsel * HDIM * HDIM))[idx] = *(uint2*)h;
        }
    }
}

// ---------------- HMMA GEMM: both relation weights in one launch -------------
__global__ __launch_bounds__(256) void gemm_mma2_kernel(const __half* __restrict__ X,
                                                        const __half* __restrict__ Wa,
                                                        const __half* __restrict__ Wb,
                                                        __half* __restrict__ Ya,
                                                        __half* __restrict__ Yb, int nrows) {
    const __half* W = blockIdx.y ? Wb : Wa;
    __half* Y       = blockIdx.y ? Yb : Ya;

    __shared__ __half Xs[128][40];
    __shared__ __half Ws[32][136];
    const int tid  = threadIdx.x;
    const int warp = tid >> 5, lane = tid & 31;
    const int row0 = blockIdx.x * 128;
    const int wrow = warp * 16;

    float acc[16][4];
#pragma unroll
    for (int t = 0; t < 16; t++)
#pragma unroll
        for (int j = 0; j < 4; j++) acc[t][j] = 0.f;

    for (int k0 = 0; k0 < HDIM; k0 += 32) {
#pragma unroll
        for (int t = tid; t < 512; t += 256) {
            int r = t >> 2, c8 = (t & 3) * 8;
            int gr = row0 + r;
            uint4 v = make_uint4(0u, 0u, 0u, 0u);
            if (gr < nrows) v = *(const uint4*)(X + (size_t)gr * HDIM + k0 + c8);
            *(uint4*)&Xs[r][c8] = v;
        }
#pragma unroll
        for (int t = tid; t < 512; t += 256) {
            int r = t >> 4, c8 = (t & 15) * 8;
            *(uint4*)&Ws[r][c8] = *(const uint4*)(W + (size_t)(k0 + r) * HDIM + c8);
        }
        __syncthreads();
#pragma unroll
        for (int ks = 0; ks < 2; ks++) {
            const int kk = ks * 16;
            uint32_t a[4];
            {
                const __half* pa = &Xs[wrow + (lane & 7) + 8 * ((lane >> 3) & 1)][kk + 8 * (lane >> 4)];
                uint32_t addr = (uint32_t)__cvta_generic_to_shared(pa);
                asm volatile("ldmatrix.sync.aligned.m8n8.x4.shared.b16 {%0,%1,%2,%3}, [%4];"
                             : "=r"(a[0]), "=r"(a[1]), "=r"(a[2]), "=r"(a[3]) : "r"(addr));
            }
#pragma unroll
            for (int nt = 0; nt < 8; nt++) {
                const int n0 = nt * 16;
                uint32_t b[4];
                const __half* pb = &Ws[kk + (lane & 7) + 8 * ((lane >> 3) & 1)][n0 + 8 * (lane >> 4)];
                uint32_t addr = (uint32_t)__cvta_generic_to_shared(pb);
                asm volatile("ldmatrix.sync.aligned.m8n8.x4.trans.shared.b16 {%0,%1,%2,%3}, [%4];"
                             : "=r"(b[0]), "=r"(b[1]), "=r"(b[2]), "=r"(b[3]) : "r"(addr));
                asm volatile("mma.sync.aligned.m16n8k16.row.col.f32.f16.f16.f32 "
                             "{%0,%1,%2,%3}, {%4,%5,%6,%7}, {%8,%9}, {%0,%1,%2,%3};"
                             : "+f"(acc[2 * nt][0]), "+f"(acc[2 * nt][1]),
                               "+f"(acc[2 * nt][2]), "+f"(acc[2 * nt][3])
                             : "r"(a[0]), "r"(a[1]), "r"(a[2]), "r"(a[3]), "r"(b[0]), "r"(b[1]));
                asm volatile("mma.sync.aligned.m16n8k16.row.col.f32.f16.f16.f32 "
                             "{%0,%1,%2,%3}, {%4,%5,%6,%7}, {%8,%9}, {%0,%1,%2,%3};"
                             : "+f"(acc[2 * nt + 1][0]), "+f"(acc[2 * nt + 1][1]),
                               "+f"(acc[2 * nt + 1][2]), "+f"(acc[2 * nt + 1][3])
                             : "r"(a[0]), "r"(a[1]), "r"(a[2]), "r"(a[3]), "r"(b[2]), "r"(b[3]));
            }
        }
        __syncthreads();
    }
    const int rlo = row0 + wrow + (lane >> 2);
    const int rhi = rlo + 8;
    const int cbase = (lane & 3) * 2;
#pragma unroll
    for (int nt = 0; nt < 16; nt++) {
        int c = nt * 8 + cbase;
        if (rlo < nrows)
            *(__half2*)(Y + (size_t)rlo * HDIM + c) = __floats2half2_rn(acc[nt][0], acc[nt][1]);
        if (rhi < nrows)
            *(__half2*)(Y + (size_t)rhi * HDIM + c) = __floats2half2_rn(acc[nt][2], acc[nt][3]);
    }
}

// ---------------- fused aggregate (fp16 gathers, fp32 accum, 8-wide MLP) -----
template <typename OutT>
__global__ void aggregate_kernel(const __half* __restrict__ hp_p, const __half* __restrict__ hp_s,
                                 const int2* __restrict__ ep, const int* __restrict__ offs_p,
                                 const int* __restrict__ deg_p,
                                 const int2* __restrict__ es, const int* __restrict__ offs_s,
                                 const int* __restrict__ deg_s,
                                 const float* __restrict__ bp, const float* __restrict__ bs,
                                 OutT* __restrict__ out, __half* __restrict__ aux, int n) {
    int w = (blockIdx.x * blockDim.x + threadIdx.x) >> 5;
    int lane = threadIdx.x & 31;
    if (w >= n) return;
    float4 v = make_float4(0.f, 0.f, 0.f, 0.f);

#pragma unroll 1
    for (int rel = 0; rel < 2; rel++) {
        const int2* ed = rel ? es : ep;
        const __half* hp = rel ? hp_s : hp_p;
        int st = rel ? offs_s[w] : offs_p[w];
        int en = st + (rel ? deg_s[w] : deg_p[w]);
        int j = st;
        // 8-deep batch: load 8 edge descriptors, then 8 independent row gathers
        for (; j + 7 < en; j += 8) {
            int2 ee[8];
            uint2 rr[8];
#pragma unroll
            for (int q = 0; q < 8; q++) ee[q] = __ldg(&ed[j + q]);
#pragma unroll
            for (int q = 0; q < 8; q++)
                rr[q] = __ldg((const uint2*)(hp + (size_t)ee[q].x * HDIM) + lane);
#pragma unroll
            for (int q = 0; q < 8; q++) {
                float c = __int_as_float(ee[q].y);
                float2 a0 = __half22float2(*(__half2*)&rr[q].x);
                float2 a1 = __half22float2(*(__half2*)&rr[q].y);
                v.x += c * a0.x; v.y += c * a0.y; v.z += c * a1.x; v.w += c * a1.y;
            }
        }
        for (; j + 3 < en; j += 4) {
            int2 ee[4];
            uint2 rr[4];
#pragma unroll
            for (int q = 0; q < 4; q++) ee[q] = __ldg(&ed[j + q]);
#pragma unroll
            for (int q = 0; q < 4; q++)
                rr[q] = __ldg((const uint2*)(hp + (size_t)ee[q].x * HDIM) + lane);
#pragma unroll
            for (int q = 0; q < 4; q++) {
                float c = __int_as_float(ee[q].y);
                float2 a0 = __half22float2(*(__half2*)&rr[q].x);
                float2 a1 = __half22float2(*(__half2*)&rr[q].y);
                v.x += c * a0.x; v.y += c * a0.y; v.z += c * a1.x; v.w += c * a1.y;
            }
        }
        for (; j < en; j++) {
            int2 e0 = __ldg(&ed[j]);
            uint2 r0 = __ldg((const uint2*)(hp + (size_t)e0.x * HDIM) + lane);
            float c0 = __int_as_float(e0.y);
            float2 a0 = __half22float2(*(__half2*)&r0.x);
            float2 a1 = __half22float2(*(__half2*)&r0.y);
            v.x += c0 * a0.x; v.y += c0 * a0.y; v.z += c0 * a1.x; v.w += c0 * a1.y;
        }
    }
    float4 b1 = ((const float4*)bp)[lane];
    float4 b2 = ((const float4*)bs)[lane];
    float4 r;
    r.x = fmaxf(0.5f * (v.x + b1.x + b2.x), 0.f);
    r.y = fmaxf(0.5f * (v.y + b1.y + b2.y), 0.f);
    r.z = fmaxf(0.5f * (v.z + b1.z + b2.z), 0.f);
    r.w = fmaxf(0.5f * (v.w + b1.w + b2.w), 0.f);
    if (sizeof(OutT) == 4) {
        *((float4*)((float*)out + (size_t)w * HDIM) + lane) = r;
        if (aux) {
            __half2 h[2];
            h[0] = __floats2half2_rn(r.x, r.y);
            h[1] = __floats2half2_rn(r.z, r.w);
            *((uint2*)(aux + (size_t)w * HDIM) + lane) = *(uint2*)h;
        }
    } else {
        __half2 h[2];
        h[0] = __floats2half2_rn(r.x, r.y);
        h[1] = __floats2half2_rn(r.z, r.w);
        *((uint2*)((__half*)out + (size_t)w * HDIM) + lane) = *(uint2*)h;
    }
}

// ---------------- pair classifier (fp16 z gather) -----------------------------
__global__ void pair_kernel(const __half* __restrict__ zh,
                            const int* __restrict__ ps, const int* __restrict__ pd,
                            const float* __restrict__ Wc, const float* __restrict__ bc,
                            float* __restrict__ out, int p) {
    int w = (blockIdx.x * blockDim.x + threadIdx.x) >> 5;
    int lane = threadIdx.x & 31;
    if (w >= p) return;
    int s = __ldg(&ps[w]), d = __ldg(&pd[w]);
    uint2 rs = __ldg((const uint2*)(zh + (size_t)s * HDIM) + lane);
    uint2 rd = __ldg((const uint2*)(zh + (size_t)d * HDIM) + lane);
    float2 zs0 = __half22float2(*(__half2*)&rs.x), zs1 = __half22float2(*(__half2*)&rs.y);
    float2 zd0 = __half22float2(*(__half2*)&rd.x), zd1 = __half22float2(*(__half2*)&rd.y);
    const float4* wc4 = (const float4*)Wc;
    float4 wa = wc4[lane * 2], wb = wc4[lane * 2 + 1];
    float l0 = zs0.x * wa.x + zs0.y * wa.z + zs1.x * wb.x + zs1.y * wb.z;
    float l1 = zs0.x * wa.y + zs0.y * wa.w + zs1.x * wb.y + zs1.y * wb.w;
    float4 wcv = wc4[64 + lane * 2], wd = wc4[64 + lane * 2 + 1];
    l0 += zd0.x * wcv.x + zd0.y * wcv.z + zd1.x * wd.x + zd1.y * wd.z;
    l1 += zd0.x * wcv.y + zd0.y * wcv.w + zd1.x * wd.y + zd1.y * wd.w;
#pragma unroll
    for (int o = 16; o; o >>= 1) {
        l0 += __shfl_xor_sync(0xffffffffu, l0, o);
        l1 += __shfl_xor_sync(0xffffffffu, l1, o);
    }
    if (lane == 0) {
        out[(size_t)w * 2] = l0 + bc[0];
        out[(size_t)w * 2 + 1] = l1 + bc[1];
    }
}

// ---------------- launch -----------------------------------------------------

extern "C" void kernel_launch(void* const* d_in, const int* in_sizes, int n_in,
                              void* d_out, int out_size) {
    const float* feat   = (const float*)d_in[0];
    const int* src_ppi  = (const int*)d_in[1];
    const int* dst_ppi  = (const int*)d_in[2];
    const int* src_sim  = (const int*)d_in[3];
    const int* dst_sim  = (const int*)d_in[4];
    const int* pair_src = (const int*)d_in[5];
    const int* pair_dst = (const int*)d_in[6];
    const float* W0_ppi = (const float*)d_in[7];
    const float* b0_ppi = (const float*)d_in[8];
    const float* W0_sim = (const float*)d_in[9];
    const float* b0_sim = (const float*)d_in[10];
    const float* W1_ppi = (const float*)d_in[11];
    const float* b1_ppi = (const float*)d_in[12];
    const float* W1_sim = (const float*)d_in[13];
    const float* b1_sim = (const float*)d_in[14];
    const float* Wc     = (const float*)d_in[15];
    const float* bc     = (const float*)d_in[16];

    const int n = in_sizes[0] / HDIM;
    const int e = in_sizes[1];
    const int p = in_sizes[5];

    float* zout   = (float*)d_out;
    float* logits = (float*)d_out + (size_t)n * HDIM;

    __half *xh, *h16, *hp_ppi, *hp_sim, *wh;
    int *ints, *offs;
    int2 *edges_p, *edges_s;
    cudaGetSymbolAddress((void**)&xh,      g_xh);
    cudaGetSymbolAddress((void**)&h16,     g_h16);
    cudaGetSymbolAddress((void**)&hp_ppi,  g_hp_ppi);
    cudaGetSymbolAddress((void**)&hp_sim,  g_hp_sim);
    cudaGetSymbolAddress((void**)&wh,      g_wh);
    cudaGetSymbolAddress((void**)&ints,    g_ints);
    cudaGetSymbolAddress((void**)&offs,    g_offs);
    cudaGetSymbolAddress((void**)&edges_p, g_edges_p);
    cudaGetSymbolAddress((void**)&edges_s, g_edges_s);

    int* deg_in_p = ints + n;
    int* deg_in_s = ints + 3 * n;
    int* offs_p = offs;
    int* offs_s = offs + NNODES;

    __half* w0p = wh;
    __half* w0s = wh + HDIM * HDIM;
    __half* w1p = wh + 2 * HDIM * HDIM;
    __half* w1s = wh + 3 * HDIM * HDIM;

    const int TB = 256;
    const int nh = n * HDIM;
    const int n4x = nh / 4;
    const int e2_blocks   = (2 * e + TB - 1) / TB;
    const int zero_blocks = (n + TB - 1) / TB;
    const int cv_blocks   = (n4x + 4 * (HDIM * HDIM / 4) + TB - 1) / TB;
    const int agg_blocks  = (int)(((long long)n * 32 + TB - 1) / TB);
    const int pair_blocks = (int)(((long long)p * 32 + TB - 1) / TB);
    dim3 gemm_grid((n + 127) / 128, 2);

    // ---- CSR build ----
    zero_ints_kernel<<<zero_blocks, TB>>>((int4*)ints, n);
    deg2_kernel<<<e2_blocks, TB>>>(src_ppi, dst_ppi, src_sim, dst_sim, ints, n, e);
    scan_full_kernel<<<2, 1024>>>(deg_in_p, deg_in_s, offs, ints, n);
    sort2_kernel<<<e2_blocks, TB>>>(src_ppi, dst_ppi, src_sim, dst_sim, ints,
                                    edges_p, edges_s, n, e);

    // ---- fp16 conversion (feat + weights) ----
    convert_all_kernel<<<cv_blocks, TB>>>(feat, xh, W0_ppi, W0_sim, W1_ppi, W1_sim, wh, n4x);

    // ---- layer 0 ----
    gemm_mma2_kernel<<<gemm_grid, 256>>>(xh, w0p, w0s, hp_ppi, hp_sim, n);
    aggregate_kernel<__half><<<agg_blocks, TB>>>(hp_ppi, hp_sim, edges_p, offs_p, deg_in_p,
                                                 edges_s, offs_s, deg_in_s, b0_ppi, b0_sim,
                                                 h16, (__half*)0, n);

    // ---- layer 1 (agg writes fp32 zout + fp16 copy into xh, now free) ----
    gemm_mma2_kernel<<<gemm_grid, 256>>>(h16, w1p, w1s, hp_ppi, hp_sim, n);
    aggregate_kernel<float><<<agg_blocks, TB>>>(hp_ppi, hp_sim, edges_p, offs_p, deg_in_p,
                                                edges_s, offs_s, deg_in_s, b1_ppi, b1_sim,
                                                zout, xh, n);

    // ---- pair classifier (fp16 z) ----
    pair_kernel<<<pair_blocks, TB>>>(xh, pair_src, pair_dst, Wc, bc, logits, p);
}

// round 14
// speedup vs baseline: 1.0286x; 1.0180x over previous
#include <cuda_runtime.h>
#include <cuda_fp16.h>
#include <cstddef>
#include <cstdint>

#define NNODES 100000
#define EDGES  1600000
#define HDIM   128

// ---------------- scratch (device globals) -----------------------------------
__device__ __align__(256) __half g_zh    [(size_t)NNODES * HDIM];   // fp16 z copy
__device__ __align__(256) __half g_h16   [(size_t)NNODES * HDIM];
__device__ __align__(256) __half g_hp_ppi[(size_t)NNODES * HDIM];
__device__ __align__(256) __half g_hp_sim[(size_t)NNODES * HDIM];
__device__ __align__(256) __half g_wh[4 * HDIM * HDIM];
__device__ __align__(256) int2   g_edges_p[EDGES];
__device__ __align__(256) int2   g_edges_s[EDGES];
// [deg_out_p | deg_in_p | deg_out_s | deg_in_s | cursor_p | cursor_s]
__device__ __align__(256) int    g_ints[6 * NNODES];
__device__ __align__(256) int    g_offs[2 * NNODES];

// ---------------- CSR build ---------------------------------------------------

__global__ void zero_ints_kernel(int4* __restrict__ p, int n4) {
    int i = blockIdx.x * blockDim.x + threadIdx.x;
    if (i < n4) p[i] = make_int4(0, 0, 0, 0);
}

__global__ void deg2_kernel(const int* __restrict__ src_p, const int* __restrict__ dst_p,
                            const int* __restrict__ src_s, const int* __restrict__ dst_s,
                            int* __restrict__ ints, int n, int e) {
    int i = blockIdx.x * blockDim.x + threadIdx.x;
    if (i < e) {
        atomicAdd(&ints[src_p[i]], 1);
        atomicAdd(&ints[n + dst_p[i]], 1);
    } else if (i < 2 * e) {
        int j = i - e;
        atomicAdd(&ints[2 * n + src_s[j]], 1);
        atomicAdd(&ints[3 * n + dst_s[j]], 1);
    }
}

// scan of deg_in per relation -> offs; also initializes cursor copy
__global__ void scan_full_kernel(const int* __restrict__ din0, const int* __restrict__ din1,
                                 int* __restrict__ offs, int* __restrict__ ints, int n) {
    const int CH = 98;
    const int* din = blockIdx.x ? din1 : din0;
    int* out  = offs + blockIdx.x * NNODES;
    int* curs = ints + (4 + blockIdx.x) * n;
    int t = threadIdx.x;
    int base = t * CH;

    int sum = 0;
    for (int k = 0; k < CH; k++) {
        int i = base + k;
        if (i < n) sum += din[i];
    }
    int lane = t & 31, wid = t >> 5;
    int incl = sum;
#pragma unroll
    for (int o = 1; o < 32; o <<= 1) {
        int v = __shfl_up_sync(0xffffffffu, incl, o);
        if (lane >= o) incl += v;
    }
    __shared__ int wsum[32];
    if (lane == 31) wsum[wid] = incl;
    __syncthreads();
    if (wid == 0) {
        int v = wsum[lane];
#pragma unroll
        for (int o = 1; o < 32; o <<= 1) {
            int u = __shfl_up_sync(0xffffffffu, v, o);
            if (lane >= o) v += u;
        }
        wsum[lane] = v;
    }
    __syncthreads();
    int run = (incl - sum) + (wid ? wsum[wid - 1] : 0);
    for (int k = 0; k < CH; k++) {
        int i = base + k;
        if (i < n) {
            out[i] = run;
            curs[i] = run;
            run += din[i];
        }
    }
}

// slot-scatter via cursor (one atomic, no offs read), both relations;
// tail blocks (i >= 2e) convert the 4 weight matrices to fp16.
__global__ void sort2_kernel(const int* __restrict__ src_p, const int* __restrict__ dst_p,
                             const int* __restrict__ src_s, const int* __restrict__ dst_s,
                             int* __restrict__ ints, int2* __restrict__ edges_p,
                             int2* __restrict__ edges_s,
                             const float* __restrict__ w0p, const float* __restrict__ w0s,
                             const float* __restrict__ w1p, const float* __restrict__ w1s,
                             __half* __restrict__ wh, int n, int e) {
    int i = blockIdx.x * blockDim.x + threadIdx.x;
    if (i < e) {
        int s = src_p[i], d = dst_p[i];
        float c = rsqrtf(fmaxf((float)ints[s], 1.0f)) * rsqrtf(fmaxf((float)ints[n + d], 1.0f));
        int slot = atomicAdd(&ints[4 * n + d], 1);
        edges_p[slot] = make_int2(s, __float_as_int(c));
    } else if (i < 2 * e) {
        int j = i - e;
        int s = src_s[j], d = dst_s[j];
        float c = rsqrtf(fmaxf((float)ints[2 * n + s], 1.0f)) * rsqrtf(fmaxf((float)ints[3 * n + d], 1.0f));
        int slot = atomicAdd(&ints[5 * n + d], 1);
        edges_s[slot] = make_int2(s, __float_as_int(c));
    } else {
        int j = i - 2 * e;                       // [0, 16384): 4 weights x 4096 float4
        if (j < 4 * (HDIM * HDIM / 4)) {
            int wsel = j >> 12, idx = j & 4095;
            const float* w = wsel == 0 ? w0p : wsel == 1 ? w0s : wsel == 2 ? w1p : w1s;
            float4 v = ((const float4*)w)[idx];
            __half2 h[2];
            h[0] = __floats2half2_rn(v.x, v.y);
            h[1] = __floats2half2_rn(v.z, v.w);
            ((uint2*)(wh + (size_t)wsel * HDIM * HDIM))[idx] = *(uint2*)h;
        }
    }
}

// ---------------- HMMA GEMM (templated input dtype), both weights ------------
template <typename InT>
__global__ __launch_bounds__(256) void gemm_mma2_kernel(const InT* __restrict__ X,
                                                        const __half* __restrict__ Wa,
                                                        const __half* __restrict__ Wb,
                                                        __half* __restrict__ Ya,
                                                        __half* __restrict__ Yb, int nrows) {
    const __half* W = blockIdx.y ? Wb : Wa;
    __half* Y       = blockIdx.y ? Yb : Ya;

    __shared__ __align__(16) __half Xs[128][40];
    __shared__ __align__(16) __half Ws[32][136];
    const int tid  = threadIdx.x;
    const int warp = tid >> 5, lane = tid & 31;
    const int row0 = blockIdx.x * 128;
    const int wrow = warp * 16;

    float acc[16][4];
#pragma unroll
    for (int t = 0; t < 16; t++)
#pragma unroll
        for (int j = 0; j < 4; j++) acc[t][j] = 0.f;

    for (int k0 = 0; k0 < HDIM; k0 += 32) {
        if (sizeof(InT) == 2) {
#pragma unroll
            for (int t = tid; t < 512; t += 256) {
                int r = t >> 2, c8 = (t & 3) * 8;
                int gr = row0 + r;
                uint4 v = make_uint4(0u, 0u, 0u, 0u);
                if (gr < nrows) v = *(const uint4*)((const __half*)X + (size_t)gr * HDIM + k0 + c8);
                *(uint4*)&Xs[r][c8] = v;
            }
        } else {
#pragma unroll
            for (int t = tid; t < 1024; t += 256) {
                int r = t >> 3, c4 = (t & 7) * 4;
                int gr = row0 + r;
                float4 v = make_float4(0.f, 0.f, 0.f, 0.f);
                if (gr < nrows) v = *(const float4*)((const float*)X + (size_t)gr * HDIM + k0 + c4);
                __half2 h[2];
                h[0] = __floats2half2_rn(v.x, v.y);
                h[1] = __floats2half2_rn(v.z, v.w);
                *(uint2*)&Xs[r][c4] = *(uint2*)h;
            }
        }
#pragma unroll
        for (int t = tid; t < 512; t += 256) {
            int r = t >> 4, c8 = (t & 15) * 8;
            *(uint4*)&Ws[r][c8] = *(const uint4*)(W + (size_t)(k0 + r) * HDIM + c8);
        }
        __syncthreads();
#pragma unroll
        for (int ks = 0; ks < 2; ks++) {
            const int kk = ks * 16;
            uint32_t a[4];
            {
                const __half* pa = &Xs[wrow + (lane & 7) + 8 * ((lane >> 3) & 1)][kk + 8 * (lane >> 4)];
                uint32_t addr = (uint32_t)__cvta_generic_to_shared(pa);
                asm volatile("ldmatrix.sync.aligned.m8n8.x4.shared.b16 {%0,%1,%2,%3}, [%4];"
                             : "=r"(a[0]), "=r"(a[1]), "=r"(a[2]), "=r"(a[3]) : "r"(addr));
            }
#pragma unroll
            for (int nt = 0; nt < 8; nt++) {
                const int n0 = nt * 16;
                uint32_t b[4];
                const __half* pb = &Ws[kk + (lane & 7) + 8 * ((lane >> 3) & 1)][n0 + 8 * (lane >> 4)];
                uint32_t addr = (uint32_t)__cvta_generic_to_shared(pb);
                asm volatile("ldmatrix.sync.aligned.m8n8.x4.trans.shared.b16 {%0,%1,%2,%3}, [%4];"
                             : "=r"(b[0]), "=r"(b[1]), "=r"(b[2]), "=r"(b[3]) : "r"(addr));
                asm volatile("mma.sync.aligned.m16n8k16.row.col.f32.f16.f16.f32 "
                             "{%0,%1,%2,%3}, {%4,%5,%6,%7}, {%8,%9}, {%0,%1,%2,%3};"
                             : "+f"(acc[2 * nt][0]), "+f"(acc[2 * nt][1]),
                               "+f"(acc[2 * nt][2]), "+f"(acc[2 * nt][3])
                             : "r"(a[0]), "r"(a[1]), "r"(a[2]), "r"(a[3]), "r"(b[0]), "r"(b[1]));
                asm volatile("mma.sync.aligned.m16n8k16.row.col.f32.f16.f16.f32 "
                             "{%0,%1,%2,%3}, {%4,%5,%6,%7}, {%8,%9}, {%0,%1,%2,%3};"
                             : "+f"(acc[2 * nt + 1][0]), "+f"(acc[2 * nt + 1][1]),
                               "+f"(acc[2 * nt + 1][2]), "+f"(acc[2 * nt + 1][3])
                             : "r"(a[0]), "r"(a[1]), "r"(a[2]), "r"(a[3]), "r"(b[2]), "r"(b[3]));
            }
        }
        __syncthreads();
    }
    const int rlo = row0 + wrow + (lane >> 2);
    const int rhi = rlo + 8;
    const int cbase = (lane & 3) * 2;
#pragma unroll
    for (int nt = 0; nt < 16; nt++) {
        int c = nt * 8 + cbase;
        if (rlo < nrows)
            *(__half2*)(Y + (size_t)rlo * HDIM + c) = __floats2half2_rn(acc[nt][0], acc[nt][1]);
        if (rhi < nrows)
            *(__half2*)(Y + (size_t)rhi * HDIM + c) = __floats2half2_rn(acc[nt][2], acc[nt][3]);
    }
}

// ---------------- fused aggregate (fp16 gathers, fp32 accum, 8-wide MLP) -----
template <typename OutT>
__global__ void aggregate_kernel(const __half* __restrict__ hp_p, const __half* __restrict__ hp_s,
                                 const int2* __restrict__ ep, const int* __restrict__ offs_p,
                                 const int* __restrict__ deg_p,
                                 const int2* __restrict__ es, const int* __restrict__ offs_s,
                                 const int* __restrict__ deg_s,
                                 const float* __restrict__ bp, const float* __restrict__ bs,
                                 OutT* __restrict__ out, __half* __restrict__ aux, int n) {
    int w = (blockIdx.x * blockDim.x + threadIdx.x) >> 5;
    int lane = threadIdx.x & 31;
    if (w >= n) return;
    float4 v = make_float4(0.f, 0.f, 0.f, 0.f);

#pragma unroll 1
    for (int rel = 0; rel < 2; rel++) {
        const int2* ed = rel ? es : ep;
        const __half* hp = rel ? hp_s : hp_p;
        int st = rel ? offs_s[w] : offs_p[w];
        int en = st + (rel ? deg_s[w] : deg_p[w]);
        int j = st;
        for (; j + 7 < en; j += 8) {
            int2 ee[8];
            uint2 rr[8];
#pragma unroll
            for (int q = 0; q < 8; q++) ee[q] = __ldg(&ed[j + q]);
#pragma unroll
            for (int q = 0; q < 8; q++)
                rr[q] = __ldg((const uint2*)(hp + (size_t)ee[q].x * HDIM) + lane);
#pragma unroll
            for (int q = 0; q < 8; q++) {
                float c = __int_as_float(ee[q].y);
                float2 a0 = __half22float2(*(__half2*)&rr[q].x);
                float2 a1 = __half22float2(*(__half2*)&rr[q].y);
                v.x += c * a0.x; v.y += c * a0.y; v.z += c * a1.x; v.w += c * a1.y;
            }
        }
        for (; j + 3 < en; j += 4) {
            int2 ee[4];
            uint2 rr[4];
#pragma unroll
            for (int q = 0; q < 4; q++) ee[q] = __ldg(&ed[j + q]);
#pragma unroll
            for (int q = 0; q < 4; q++)
                rr[q] = __ldg((const uint2*)(hp + (size_t)ee[q].x * HDIM) + lane);
#pragma unroll
            for (int q = 0; q < 4; q++) {
                float c = __int_as_float(ee[q].y);
                float2 a0 = __half22float2(*(__half2*)&rr[q].x);
                float2 a1 = __half22float2(*(__half2*)&rr[q].y);
                v.x += c * a0.x; v.y += c * a0.y; v.z += c * a1.x; v.w += c * a1.y;
            }
        }
        for (; j < en; j++) {
            int2 e0 = __ldg(&ed[j]);
            uint2 r0 = __ldg((const uint2*)(hp + (size_t)e0.x * HDIM) + lane);
            float c0 = __int_as_float(e0.y);
            float2 a0 = __half22float2(*(__half2*)&r0.x);
            float2 a1 = __half22float2(*(__half2*)&r0.y);
            v.x += c0 * a0.x; v.y += c0 * a0.y; v.z += c0 * a1.x; v.w += c0 * a1.y;
        }
    }
    float4 b1 = ((const float4*)bp)[lane];
    float4 b2 = ((const float4*)bs)[lane];
    float4 r;
    r.x = fmaxf(0.5f * (v.x + b1.x + b2.x), 0.f);
    r.y = fmaxf(0.5f * (v.y + b1.y + b2.y), 0.f);
    r.z = fmaxf(0.5f * (v.z + b1.z + b2.z), 0.f);
    r.w = fmaxf(0.5f * (v.w + b1.w + b2.w), 0.f);
    if (sizeof(OutT) == 4) {
        *((float4*)((float*)out + (size_t)w * HDIM) + lane) = r;
        if (aux) {
            __half2 h[2];
            h[0] = __floats2half2_rn(r.x, r.y);
            h[1] = __floats2half2_rn(r.z, r.w);
            *((uint2*)(aux + (size_t)w * HDIM) + lane) = *(uint2*)h;
        }
    } else {
        __half2 h[2];
        h[0] = __floats2half2_rn(r.x, r.y);
        h[1] = __floats2half2_rn(r.z, r.w);
        *((uint2*)((__half*)out + (size_t)w * HDIM) + lane) = *(uint2*)h;
    }
}

// ---------------- pair classifier (fp16 z gather) -----------------------------
__global__ void pair_kernel(const __half* __restrict__ zh,
                            const int* __restrict__ ps, const int* __restrict__ pd,
                            const float* __restrict__ Wc, const float* __restrict__ bc,
                            float* __restrict__ out, int p) {
    int w = (blockIdx.x * blockDim.x + threadIdx.x) >> 5;
    int lane = threadIdx.x & 31;
    if (w >= p) return;
    int s = __ldg(&ps[w]), d = __ldg(&pd[w]);
    uint2 rs = __ldg((const uint2*)(zh + (size_t)s * HDIM) + lane);
    uint2 rd = __ldg((const uint2*)(zh + (size_t)d * HDIM) + lane);
    float2 zs0 = __half22float2(*(__half2*)&rs.x), zs1 = __half22float2(*(__half2*)&rs.y);
    float2 zd0 = __half22float2(*(__half2*)&rd.x), zd1 = __half22float2(*(__half2*)&rd.y);
    const float4* wc4 = (const float4*)Wc;
    float4 wa = wc4[lane * 2], wb = wc4[lane * 2 + 1];
    float l0 = zs0.x * wa.x + zs0.y * wa.z + zs1.x * wb.x + zs1.y * wb.z;
    float l1 = zs0.x * wa.y + zs0.y * wa.w + zs1.x * wb.y + zs1.y * wb.w;
    float4 wcv = wc4[64 + lane * 2], wd = wc4[64 + lane * 2 + 1];
    l0 += zd0.x * wcv.x + zd0.y * wcv.z + zd1.x * wd.x + zd1.y * wd.z;
    l1 += zd0.x * wcv.y + zd0.y * wcv.w + zd1.x * wd.y + zd1.y * wd.w;
#pragma unroll
    for (int o = 16; o; o >>= 1) {
        l0 += __shfl_xor_sync(0xffffffffu, l0, o);
        l1 += __shfl_xor_sync(0xffffffffu, l1, o);
    }
    if (lane == 0) {
        out[(size_t)w * 2] = l0 + bc[0];
        out[(size_t)w * 2 + 1] = l1 + bc[1];
    }
}

// ---------------- launch -----------------------------------------------------

extern "C" void kernel_launch(void* const* d_in, const int* in_sizes, int n_in,
                              void* d_out, int out_size) {
    const float* feat   = (const float*)d_in[0];
    const int* src_ppi  = (const int*)d_in[1];
    const int* dst_ppi  = (const int*)d_in[2];
    const int* src_sim  = (const int*)d_in[3];
    const int* dst_sim  = (const int*)d_in[4];
    const int* pair_src = (const int*)d_in[5];
    const int* pair_dst = (const int*)d_in[6];
    const float* W0_ppi = (const float*)d_in[7];
    const float* b0_ppi = (const float*)d_in[8];
    const float* W0_sim = (const float*)d_in[9];
    const float* b0_sim = (const float*)d_in[10];
    const float* W1_ppi = (const float*)d_in[11];
    const float* b1_ppi = (const float*)d_in[12];
    const float* W1_sim = (const float*)d_in[13];
    const float* b1_sim = (const float*)d_in[14];
    const float* Wc     = (const float*)d_in[15];
    const float* bc     = (const float*)d_in[16];

    const int n = in_sizes[0] / HDIM;
    const int e = in_sizes[1];
    const int p = in_sizes[5];

    float* zout   = (float*)d_out;
    float* logits = (float*)d_out + (size_t)n * HDIM;

    __half *zh, *h16, *hp_ppi, *hp_sim, *wh;
    int *ints, *offs;
    int2 *edges_p, *edges_s;
    cudaGetSymbolAddress((void**)&zh,      g_zh);
    cudaGetSymbolAddress((void**)&h16,     g_h16);
    cudaGetSymbolAddress((void**)&hp_ppi,  g_hp_ppi);
    cudaGetSymbolAddress((void**)&hp_sim,  g_hp_sim);
    cudaGetSymbolAddress((void**)&wh,      g_wh);
    cudaGetSymbolAddress((void**)&ints,    g_ints);
    cudaGetSymbolAddress((void**)&offs,    g_offs);
    cudaGetSymbolAddress((void**)&edges_p, g_edges_p);
    cudaGetSymbolAddress((void**)&edges_s, g_edges_s);

    int* deg_in_p = ints + n;
    int* deg_in_s = ints + 3 * n;
    int* offs_p = offs;
    int* offs_s = offs + NNODES;

    __half* w0p = wh;
    __half* w0s = wh + HDIM * HDIM;
    __half* w1p = wh + 2 * HDIM * HDIM;
    __half* w1s = wh + 3 * HDIM * HDIM;

    const int TB = 256;
    const int e2_blocks   = (2 * e + TB - 1) / TB;
    const int wconv_elems = 4 * (HDIM * HDIM / 4);              // 16384 float4s
    const int sort_blocks = (2 * e + wconv_elems + TB - 1) / TB; // edges + weight tail
    const int zero_blocks = (n + TB - 1) / TB;
    const int agg_blocks  = (int)(((long long)n * 32 + TB - 1) / TB);
    const int pair_blocks = (int)(((long long)p * 32 + TB - 1) / TB);
    dim3 gemm_grid((n + 127) / 128, 2);

    // ---- CSR build (+ weight fp16 conversion in sort tail) ----
    zero_ints_kernel<<<zero_blocks, TB>>>((int4*)ints, n);
    deg2_kernel<<<e2_blocks, TB>>>(src_ppi, dst_ppi, src_sim, dst_sim, ints, n, e);
    scan_full_kernel<<<2, 1024>>>(deg_in_p, deg_in_s, offs, ints, n);
    sort2_kernel<<<sort_blocks, TB>>>(src_ppi, dst_ppi, src_sim, dst_sim, ints,
                                      edges_p, edges_s,
                                      W0_ppi, W0_sim, W1_ppi, W1_sim, wh, n, e);

    // ---- layer 0 (GEMM reads fp32 feat directly, converts inline) ----
    gemm_mma2_kernel<float><<<gemm_grid, 256>>>(feat, w0p, w0s, hp_ppi, hp_sim, n);
    aggregate_kernel<__half><<<agg_blocks, TB>>>(hp_ppi, hp_sim, edges_p, offs_p, deg_in_p,
                                                 edges_s, offs_s, deg_in_s, b0_ppi, b0_sim,
                                                 h16, (__half*)0, n);

    // ---- layer 1 (agg writes fp32 zout + fp16 z copy) ----
    gemm_mma2_kernel<__half><<<gemm_grid, 256>>>(h16, w1p, w1s, hp_ppi, hp_sim, n);
    aggregate_kernel<float><<<agg_blocks, TB>>>(hp_ppi, hp_sim, edges_p, offs_p, deg_in_p,
                                                edges_s, offs_s, deg_in_s, b1_ppi, b1_sim,
                                                zout, zh, n);

    // ---- pair classifier (fp16 z) ----
    pair_kernel<<<pair_blocks, TB>>>(zh, pair_src, pair_dst, Wc, bc, logits, p);
}